// round 16
// baseline (speedup 1.0000x reference)
#include <cuda_runtime.h>
#include <cuda_fp16.h>
#include <cstdint>
#include <math.h>

#define H      1024
#define E      16
#define T      8192
#define TOPK   6
#define EPSV   1e-10f

// ---- main GEMM: BM=128, BN=128, BK=64; 128 thr, 4 warps (2x2), warptile 64x64
#define BM 128
#define BN 128
#define BK 64
#define NCHUNK (H/BK)           // 16
#define STAGES 3
#define ASTG (128*128)          // 16384
#define BSTG (64*256)           // 16384
#define STGB (ASTG+BSTG)        // 32768
#define DSMEM (STAGES*STGB + 256)
#define NPERS 304               // persistent CTAs: 2 x 152 SMs

// ---- router mini-GEMM (hi/lo split) + fused topk ----
#define LSTG   32768
#define LBOFF  (3*LSTG)
#define LTOPK  (LBOFF + 2*32768)
#define LDSMEM (LTOPK + 128*17*4 + 256)

// ---- device globals ----
__device__ int    d_counts[E];
__device__ int    d_tile_start[E + 1];
__device__ int    d_total_work;
__device__ int    d_work;
__device__ int    d_perm_token[E*T];
__device__ int    d_perm_dest [E*T];
__device__ float  d_perm_coef [E*T];
__device__ float  d_bias[T];
__device__ __half d_x16[(size_t)T*H];
__device__ __half d_xlo[(size_t)T*H];
__device__ __half d_w16[(size_t)E*H*H];
__device__ __half d_scratch16[(size_t)T*TOPK*H];

// ============================================================
__device__ __forceinline__ uint32_t smem_u32(const void* p) {
    uint32_t a;
    asm("{ .reg .u64 t; cvta.to.shared.u64 t, %1; cvt.u32.u64 %0, t; }"
        : "=r"(a) : "l"(p));
    return a;
}
__device__ __forceinline__ uint32_t pk(float a, float b) {
    __half2 h = __floats2half2_rn(a, b);
    return *(uint32_t*)&h;
}
__device__ __forceinline__ void ldsm4(uint32_t addr, uint32_t* r) {
    asm volatile("ldmatrix.sync.aligned.m8n8.x4.shared.b16 {%0,%1,%2,%3}, [%4];"
        : "=r"(r[0]), "=r"(r[1]), "=r"(r[2]), "=r"(r[3]) : "r"(addr));
}
__device__ __forceinline__ void ldsm4t(uint32_t addr, uint32_t* r) {
    asm volatile("ldmatrix.sync.aligned.m8n8.x4.trans.shared.b16 {%0,%1,%2,%3}, [%4];"
        : "=r"(r[0]), "=r"(r[1]), "=r"(r[2]), "=r"(r[3]) : "r"(addr));
}
__device__ __forceinline__ void mma16816(float* c, const uint32_t* a,
                                         uint32_t b0, uint32_t b1) {
    asm volatile(
        "mma.sync.aligned.m16n8k16.row.col.f32.f16.f16.f32 "
        "{%0,%1,%2,%3}, {%4,%5,%6,%7}, {%8,%9}, {%0,%1,%2,%3};\n"
        : "+f"(c[0]), "+f"(c[1]), "+f"(c[2]), "+f"(c[3])
        : "r"(a[0]), "r"(a[1]), "r"(a[2]), "r"(a[3]), "r"(b0), "r"(b1));
}
__device__ __forceinline__ void cpa16(uint32_t dst, const void* src) {
    asm volatile("cp.async.cg.shared.global [%0], [%1], 16;"
                 :: "r"(dst), "l"(src) : "memory");
}
#define CP_COMMIT() asm volatile("cp.async.commit_group;" ::: "memory")
#define CP_WAIT1()  asm volatile("cp.async.wait_group 1;"  ::: "memory")

// ============================================================
// Merged conversion kernel: blocks [0, WB) convert W, blocks [WB, WB+XB) do
// x -> hi/lo. Block 0 zeroes counts.
#define WB ((int)(((size_t)E*H*H) / (256*8)))   // 8192
#define XB ((int)(((size_t)T*H)   / (256*8)))   // 4096

__global__ void __launch_bounds__(256) cvt_all_kernel(const float* __restrict__ ew,
                                                      const float* __restrict__ tokens) {
    if (blockIdx.x == 0 && threadIdx.x < E) d_counts[threadIdx.x] = 0;
    if (blockIdx.x < WB) {
        const size_t i = ((size_t)blockIdx.x * 256 + threadIdx.x) * 8;
        const float4 a = *(const float4*)(ew + i);
        const float4 b = *(const float4*)(ew + i + 4);
        uint4 u;
        u.x = pk(a.x, a.y); u.y = pk(a.z, a.w);
        u.z = pk(b.x, b.y); u.w = pk(b.z, b.w);
        *(uint4*)(d_w16 + i) = u;
    } else {
        const size_t i = ((size_t)(blockIdx.x - WB) * 256 + threadIdx.x) * 8;
        float v[8];
        *(float4*)(v)     = *(const float4*)(tokens + i);
        *(float4*)(v + 4) = *(const float4*)(tokens + i + 4);
        __half hi[8];
        float  lo[8];
        #pragma unroll
        for (int j = 0; j < 8; ++j) {
            hi[j] = __float2half(v[j]);
            lo[j] = v[j] - __half2float(hi[j]);
        }
        *(uint4*)(d_x16 + i) = *(const uint4*)hi;
        uint4 ul;
        ul.x = pk(lo[0], lo[1]); ul.y = pk(lo[2], lo[3]);
        ul.z = pk(lo[4], lo[5]); ul.w = pk(lo[6], lo[7]);
        *(uint4*)(d_xlo + i) = ul;
    }
}

// ============================================================
// Router: hi/lo-split logits MMA + fused softmax/topk/scatter (UNCHANGED).
__global__ void __launch_bounds__(256) router_kernel(const float* __restrict__ rw,
                                                     const float* __restrict__ rb)
{
    const int mBase = blockIdx.x * 128;

    extern __shared__ char dsm[];
    char* sb = dsm + ((256 - (((uintptr_t)dsm) & 255)) & 255);
    const uint32_t sbase = smem_u32(sb);
    float* larr = (float*)(sb + LTOPK);

    const int tid  = threadIdx.x;
    const int lane = tid & 31;
    const int wid  = tid >> 5;
    const int h    = lane >> 4;

    {
        const int e = tid >> 4;
        const int kb = (tid & 15) * 4;
        #pragma unroll
        for (int c = 0; c < 16; ++c) {
            const int k = c * 64 + kb;
            const float4 v = *(const float4*)(rw + e * H + k);
            const float vv[4] = {v.x, v.y, v.z, v.w};
            #pragma unroll
            for (int j = 0; j < 4; ++j) {
                const int kk = k + j;
                const uint32_t off = kk * 32
                    + ((((e >> 3) ^ ((kk >> 2) & 1))) << 4) + (e & 7) * 2;
                const __half hh = __float2half(vv[j]);
                const __half hl = __float2half(vv[j] - __half2float(hh));
                *(__half*)(sb + LBOFF + off)         = hh;
                *(__half*)(sb + LBOFF + 32768 + off) = hl;
            }
        }
    }

    const int a_row0 = tid >> 3;
    const int a_c    = tid & 7;
    const uint32_t a_dst0 = a_row0 * 128 + ((a_c ^ (a_row0 & 7)) << 4);
    const size_t a_goff = (size_t)(mBase + a_row0) * H + a_c * 8;

    const int arow = wid * 16 + (lane & 15);
    const uint32_t arowbase = sbase + arow * 128;
    const uint32_t as0 = (uint32_t)(h ^ (arow & 7));

    const int bk = lane & 15;
    const uint32_t bbase0 = sbase + LBOFF + bk * 32;
    const uint32_t bx0 = (uint32_t)(h ^ ((bk >> 2) & 1));

    __syncthreads();

    #pragma unroll
    for (int s = 0; s < 2; ++s) {
        const uint32_t so = sbase + s * LSTG;
        #pragma unroll
        for (int j = 0; j < 4; ++j) {
            cpa16(so + a_dst0 + j * 4096,         d_x16 + a_goff + (size_t)32 * j * H + s * 64);
            cpa16(so + 16384 + a_dst0 + j * 4096, d_xlo + a_goff + (size_t)32 * j * H + s * 64);
        }
        CP_COMMIT();
    }

    float c[2][4];
    #pragma unroll
    for (int nt = 0; nt < 2; ++nt)
        #pragma unroll
        for (int q = 0; q < 4; ++q) c[nt][q] = 0.f;

    int stage = 0, pstage = 2;
    for (int kt = 0; kt < 16; ++kt) {
        CP_WAIT1();
        __syncthreads();

        const int nc = kt + 2;
        if (nc < 16) {
            const uint32_t so = sbase + pstage * LSTG;
            #pragma unroll
            for (int j = 0; j < 4; ++j) {
                cpa16(so + a_dst0 + j * 4096,         d_x16 + a_goff + (size_t)32 * j * H + nc * 64);
                cpa16(so + 16384 + a_dst0 + j * 4096, d_xlo + a_goff + (size_t)32 * j * H + nc * 64);
            }
        }
        CP_COMMIT();

        const uint32_t bofs = stage * LSTG;
        #pragma unroll
        for (int g = 0; g < 4; ++g) {
            uint32_t afh[4], afl[4];
            const uint32_t aslot = (((g << 1) ^ as0) << 4);
            ldsm4(arowbase + bofs + aslot, afh);
            ldsm4(arowbase + bofs + 16384 + aslot, afl);
            const uint32_t bo = (kt * 64 + g * 16) * 32 + (bx0 << 4);
            uint32_t bh[4], bl[4];
            ldsm4t(bbase0 + bo, bh);
            ldsm4t(bbase0 + 32768 + bo, bl);
            mma16816(c[0], afh, bh[0], bh[1]);
            mma16816(c[1], afh, bh[2], bh[3]);
            mma16816(c[0], afh, bl[0], bl[1]);
            mma16816(c[1], afh, bl[2], bl[3]);
            mma16816(c[0], afl, bh[0], bh[1]);
            mma16816(c[1], afl, bh[2], bh[3]);
        }

        if (++stage == 3)  stage = 0;
        if (++pstage == 3) pstage = 0;
    }

    {
        const int r0 = wid * 16 + (lane >> 2);
        #pragma unroll
        for (int nt = 0; nt < 2; ++nt) {
            const int e0 = nt * 8 + (lane & 3) * 2;
            larr[r0 * 17 + e0]           = c[nt][0];
            larr[r0 * 17 + e0 + 1]       = c[nt][1];
            larr[(r0 + 8) * 17 + e0]     = c[nt][2];
            larr[(r0 + 8) * 17 + e0 + 1] = c[nt][3];
        }
    }
    __syncthreads();

    if (tid < 128) {
        const int t = mBase + tid;
        float pv[E];
        #pragma unroll
        for (int e = 0; e < E; ++e) pv[e] = larr[tid * 17 + e] + rb[e];

        float m = pv[0];
        #pragma unroll
        for (int e = 1; e < E; ++e) m = fmaxf(m, pv[e]);
        float Z = 0.f;
        #pragma unroll
        for (int e = 0; e < E; ++e) { pv[e] = expf(pv[e] - m); Z += pv[e]; }

        int   ids[TOPK];
        float ps [TOPK];
        float ssum = 0.f;
        #pragma unroll
        for (int k = 0; k < TOPK; ++k) {
            int best = 0; float bv = pv[0];
            #pragma unroll
            for (int e = 1; e < E; ++e)
                if (pv[e] > bv) { bv = pv[e]; best = e; }
            ids[k] = best; ps[k] = bv; pv[best] = -1.f; ssum += bv;
        }

        uint32_t mymask = 0;
        #pragma unroll
        for (int k = 0; k < TOPK; ++k) mymask |= (1u << ids[k]);

        #pragma unroll
        for (int e = 0; e < E; ++e) {
            const uint32_t vote = __ballot_sync(0xffffffffu, (mymask >> e) & 1u);
            if (vote) {
                const int leader = __ffs(vote) - 1;
                int base = 0;
                if (lane == leader) base = atomicAdd(&d_counts[e], __popc(vote));
                base = __shfl_sync(0xffffffffu, base, leader);
                if ((mymask >> e) & 1u) {
                    const int pos = base + __popc(vote & ((1u << lane) - 1u));
                    int kk = 0;
                    #pragma unroll
                    for (int k = 0; k < TOPK; ++k) if (ids[k] == e) kk = k;
                    d_perm_token[e * T + pos] = t;
                    d_perm_dest [e * T + pos] = t * TOPK + kk;
                    d_perm_coef [e * T + pos] = ps[kk] / ssum;
                }
            }
        }

        const float sn = ssum / Z;
        d_bias[t] = EPSV * sn / (sn + EPSV);
    }
}

// ============================================================
// Work-queue prefix: exclusive prefix of per-expert m-tile counts.
__global__ void prefix_kernel() {
    if (threadIdx.x == 0) {
        int acc = 0;
        #pragma unroll
        for (int e = 0; e < E; ++e) {
            d_tile_start[e] = acc;
            acc += (d_counts[e] + BM - 1) / BM;
        }
        d_tile_start[E] = acc;
        d_total_work = acc * 8;
        d_work = 0;
    }
}

// ============================================================
// Persistent grouped GEMM: 304 CTAs pop compacted tiles from a work queue.
// Tile body identical to R15 (tensor-validated geometry).
__global__ void __launch_bounds__(128, 2) moe_gemm_kernel()
{
    extern __shared__ char dsm[];
    char* sb = dsm + ((256 - (((uintptr_t)dsm) & 255)) & 255);
    const uint32_t sbase = smem_u32(sb);
    __shared__ int s_w;

    const int tid  = threadIdx.x;
    const int lane = tid & 31;
    const int wid  = tid >> 5;
    const int wm   = wid >> 1;
    const int wn   = wid & 1;

    // tile-invariant pieces
    const int a_row0 = tid >> 3;               // 0..15
    const int a_c    = tid & 7;
    const uint32_t a_dst0 = a_row0 * 128 + ((a_c ^ (a_row0 & 7)) << 4);
    const int b_k0 = tid >> 4;                 // 0..7
    const int b_ch = tid & 15;
    const uint32_t b_dst0 = ASTG + b_k0 * 256 + ((b_ch ^ (b_k0 & 7)) << 4);

    const int h = lane >> 4;
    const uint32_t as0 = (uint32_t)(h ^ (lane & 7));
    const uint32_t arowbase0 = sbase + (wm * 64 + (lane & 15)) * 128;
    uint32_t boff0[4];
    {
        const int k = lane & 15;
        #pragma unroll
        for (int p = 0; p < 4; ++p) {
            const int ch = wn * 8 + p * 2 + h;
            boff0[p] = sbase + ASTG + k * 256 + ((ch ^ (k & 7)) << 4);
        }
    }

    for (;;) {
        // Barrier also protects stage-smem reuse across work items.
        if (tid == 0) s_w = atomicAdd(&d_work, 1);
        __syncthreads();
        const int w = s_w;
        if (w >= d_total_work) break;

        // decode: tidx -> expert via prefix scan; n from low bits
        const int tidx = w >> 3;
        int e = 0;
        #pragma unroll
        for (int i = 1; i < E; ++i)
            if (d_tile_start[i] <= tidx) e = i;
        const int cnt   = d_counts[e];
        const int mBase = (tidx - d_tile_start[e]) * BM;
        const int nBase = (w & 7) * BN;

        const __half* Wp   = d_w16 + (size_t)e * H * H;
        const int*    ptok = d_perm_token + e * T;

        uint32_t a_off[8];
        #pragma unroll
        for (int j = 0; j < 8; ++j) {
            const int gm = mBase + a_row0 + 16 * j;
            const int tok = ptok[(gm < cnt) ? gm : (cnt - 1)];
            a_off[j] = (uint32_t)(tok * H + a_c * 8);
        }
        const __half* b_src0 = Wp + (size_t)b_k0 * H + nBase + b_ch * 8;

        // prologue
        #pragma unroll
        for (int s = 0; s < STAGES - 1; ++s) {
            const uint32_t so = sbase + s * STGB;
            #pragma unroll
            for (int j = 0; j < 8; ++j) {
                cpa16(so + a_dst0 + j * 2048, d_x16 + a_off[j] + s * BK);
                cpa16(so + b_dst0 + j * 2048, b_src0 + (size_t)(8 * j + s * BK) * H);
            }
            CP_COMMIT();
        }

        float c[4][8][4];
        #pragma unroll
        for (int mt = 0; mt < 4; ++mt)
            #pragma unroll
            for (int nt = 0; nt < 8; ++nt)
                #pragma unroll
                for (int q = 0; q < 4; ++q) c[mt][nt][q] = 0.f;

        int stage = 0, pstage = STAGES - 1;
        for (int kt = 0; kt < NCHUNK; ++kt) {
            CP_WAIT1();
            __syncthreads();

            const int nc = kt + STAGES - 1;
            if (nc < NCHUNK) {
                const uint32_t so = sbase + pstage * STGB;
                #pragma unroll
                for (int j = 0; j < 8; ++j) {
                    cpa16(so + a_dst0 + j * 2048, d_x16 + a_off[j] + nc * BK);
                    cpa16(so + b_dst0 + j * 2048, b_src0 + (size_t)(8 * j + nc * BK) * H);
                }
            }
            CP_COMMIT();

            const uint32_t bofs = stage * STGB;
            #pragma unroll
            for (int g = 0; g < 4; ++g) {
                uint32_t afr[4][4];
                const uint32_t aslot = (((g << 1) ^ as0) << 4);
                #pragma unroll
                for (int mt = 0; mt < 4; ++mt)
                    ldsm4(arowbase0 + mt * 2048 + bofs + aslot, afr[mt]);
                #pragma unroll
                for (int pp = 0; pp < 2; ++pp) {
                    uint32_t bfr[2][4];
                    ldsm4t(boff0[pp * 2 + 0] + bofs + g * 4096, bfr[0]);
                    ldsm4t(boff0[pp * 2 + 1] + bofs + g * 4096, bfr[1]);
                    #pragma unroll
                    for (int q = 0; q < 2; ++q) {
                        const int p = pp * 2 + q;
                        #pragma unroll
                        for (int mt = 0; mt < 4; ++mt) {
                            mma16816(c[mt][p * 2 + 0], afr[mt], bfr[q][0], bfr[q][1]);
                            mma16816(c[mt][p * 2 + 1], afr[mt], bfr[q][2], bfr[q][3]);
                        }
                    }
                }
            }

            if (++stage == STAGES)  stage = 0;
            if (++pstage == STAGES) pstage = 0;
        }

        // epilogue
        #pragma unroll
        for (int mt = 0; mt < 4; ++mt) {
            #pragma unroll
            for (int half = 0; half < 2; ++half) {
                const int r  = wm * 64 + mt * 16 + (lane >> 2) + half * 8;
                const int gm = mBase + r;
                if (gm < cnt) {
                    const int   dest = d_perm_dest[e * T + gm];
                    const float coef = d_perm_coef[e * T + gm];
                    __half* orow = d_scratch16 + (size_t)dest * H + nBase;
                    #pragma unroll
                    for (int nt = 0; nt < 8; ++nt) {
                        const int col = wn * 64 + nt * 8 + (lane & 3) * 2;
                        *(uint32_t*)(orow + col) =
                            pk(c[mt][nt][half * 2 + 0] * coef,
                               c[mt][nt][half * 2 + 1] * coef);
                    }
                }
            }
        }
    }
}

// ============================================================
// Reduce (R12-exact: 8 elems/thread, 4096 blocks, ~20.5us @ DRAM roofline)
__global__ void __launch_bounds__(256) reduce_kernel(float* __restrict__ out)
{
    const int gid = blockIdx.x * blockDim.x + threadIdx.x;
    const int t   = gid >> 7;
    const int c8  = gid & 127;
    const __half* base = d_scratch16 + (size_t)t * TOPK * H + c8 * 8;

    float acc[8];
    #pragma unroll
    for (int j = 0; j < 8; ++j) acc[j] = 0.f;
    #pragma unroll
    for (int k = 0; k < TOPK; ++k) {
        const uint4 v = *(const uint4*)(base + (size_t)k * H);
        const uint32_t w[4] = {v.x, v.y, v.z, v.w};
        #pragma unroll
        for (int j = 0; j < 4; ++j) {
            const float2 f = __half22float2(*(const __half2*)&w[j]);
            acc[j * 2 + 0] += f.x;
            acc[j * 2 + 1] += f.y;
        }
    }
    const float bi = d_bias[t];
    float* op = out + (size_t)t * H + c8 * 8;
    float4 o0, o1;
    o0.x = acc[0] + bi; o0.y = acc[1] + bi; o0.z = acc[2] + bi; o0.w = acc[3] + bi;
    o1.x = acc[4] + bi; o1.y = acc[5] + bi; o1.z = acc[6] + bi; o1.w = acc[7] + bi;
    *(float4*)(op)     = o0;
    *(float4*)(op + 4) = o1;
}

// ============================================================
extern "C" void kernel_launch(void* const* d_in, const int* in_sizes, int n_in,
                              void* d_out, int out_size)
{
    const float* tokens = (const float*)d_in[0];
    const float* rw     = (const float*)d_in[1];
    const float* rb     = (const float*)d_in[2];
    const float* ew     = (const float*)d_in[3];
    float* out = (float*)d_out;

    cudaFuncSetAttribute(moe_gemm_kernel,
                         cudaFuncAttributeMaxDynamicSharedMemorySize, DSMEM);
    cudaFuncSetAttribute(router_kernel,
                         cudaFuncAttributeMaxDynamicSharedMemorySize, LDSMEM);

    cvt_all_kernel<<<WB + XB, 256>>>(ew, tokens);
    router_kernel<<<T / 128, 256, LDSMEM>>>(rw, rb);
    prefix_kernel<<<1, 32>>>();
    moe_gemm_kernel<<<NPERS, 128, DSMEM>>>();
    reduce_kernel<<<(T * H / 8) / 256, 256>>>(out);
}